// round 8
// baseline (speedup 1.0000x reference)
#include <cuda_runtime.h>
#include <cuda_bf16.h>
#include <math.h>
#include <stdint.h>

#define EMBED 768
#define FF    3072
#define BATCH 8
#define SEQ   1024
#define TOK   (BATCH * SEQ)   // 8192
#define NQKV  (3 * EMBED)     // 2304

typedef __nv_bfloat16 bf16;

// ============================ scratch buffers ================================
__device__ __align__(16) bf16  g_xhi[TOK * EMBED],  g_xlo[TOK * EMBED];
__device__ __align__(16) bf16  g_Wqkvh[(long)NQKV * EMBED], g_Wqkvl[(long)NQKV * EMBED];
__device__ __align__(16) float g_bqkv[NQKV];
__device__ __align__(16) bf16  g_W1Th[(long)FF * EMBED], g_W1Tl[(long)FF * EMBED];
__device__ __align__(16) bf16  g_W2Th[(long)EMBED * FF], g_W2Tl[(long)EMBED * FF];
__device__ __align__(16) bf16  g_QKVh[(long)TOK * NQKV], g_QKVl[(long)TOK * NQKV];
__device__ __align__(16) bf16  g_VTh[(long)BATCH * EMBED * SEQ], g_VTl[(long)BATCH * EMBED * SEQ];
__device__ __align__(16) float g_S[(long)BATCH * SEQ * SEQ];
__device__ __align__(16) bf16  g_Phi[(long)BATCH * SEQ * SEQ], g_Plo[(long)BATCH * SEQ * SEQ];
__device__ __align__(16) float g_attnP[2L * TOK * EMBED];
__device__ __align__(16) float g_x1[TOK * EMBED];
__device__ __align__(16) bf16  g_x1hi[TOK * EMBED], g_x1lo[TOK * EMBED];
__device__ __align__(16) bf16  g_hhi[(long)TOK * FF], g_hlo[(long)TOK * FF];
__device__ __align__(16) float g_fP[3L * TOK * EMBED];

// ============================ PTX helpers ====================================
__device__ __forceinline__ uint32_t smem_u32(const void* p) {
    uint32_t a;
    asm("{ .reg .u64 t; cvta.to.shared.u64 t, %1; cvt.u32.u64 %0, t; }" : "=r"(a) : "l"(p));
    return a;
}
__device__ __forceinline__ void cp16(uint32_t dst, const void* src) {
    asm volatile("cp.async.cg.shared.global [%0], [%1], 16;" :: "r"(dst), "l"(src));
}
#define CP_COMMIT() asm volatile("cp.async.commit_group;" ::: "memory")

__device__ __forceinline__ void ldm_x4(uint32_t* r, uint32_t addr) {
    asm volatile("ldmatrix.sync.aligned.m8n8.x4.shared.b16 {%0,%1,%2,%3}, [%4];"
                 : "=r"(r[0]), "=r"(r[1]), "=r"(r[2]), "=r"(r[3]) : "r"(addr));
}
__device__ __forceinline__ void mma16816(float* d, const uint32_t* a, uint32_t b0, uint32_t b1) {
    asm volatile(
        "mma.sync.aligned.m16n8k16.row.col.f32.bf16.bf16.f32 "
        "{%0,%1,%2,%3}, {%4,%5,%6,%7}, {%8,%9}, {%0,%1,%2,%3};"
        : "+f"(d[0]), "+f"(d[1]), "+f"(d[2]), "+f"(d[3])
        : "r"(a[0]), "r"(a[1]), "r"(a[2]), "r"(a[3]), "r"(b0), "r"(b1));
}
#define SWZ128(o) ((o) ^ (((o) >> 3) & 0x70))

__device__ __forceinline__ float gelu_exact(float v) {
    return 0.5f * v * (1.0f + erff(v * 0.7071067811865475f));
}

// ============================ mma GEMM =======================================
// C[M,N] = (Ahi+Alo)[M,K] @ (Bhi+Blo)[N,K]^T  (both K-major row-major)
// CTA 256x128, 512 threads, warp grid 4Mx4N (warp tile 64x32).
// BK=32, 4 stages x 48KB (A 32K + B 16K), single barrier per chunk,
// loads issued 3 chunks ahead. Each 128B smem row = [hi 64B | lo 64B], SW128.
// blockIdx.z = batch*ksplit + split;  K = per-split K length.
// EPI: 0 bias->fp32 | 1 bias->(hi,lo) | 2 scale->fp32 | 3 bias+gelu->(hi,lo)
// VOUT (with EPI=1): CTAs with col0>=1536 write transposed VT hi/lo instead.
#define BT_M 256
#define BT_N 128
#define BK   32
#define BSTAGE 49152
#define BSMEM_TOTAL (4 * BSTAGE)

template <int EPI, bool VOUT>
__global__ __launch_bounds__(512, 1)
void mma_gemm_big(const bf16* __restrict__ Ahi, const bf16* __restrict__ Alo, long ldA, long bsA,
                  const bf16* __restrict__ Bhi, const bf16* __restrict__ Blo, long ldB, long bsB,
                  float* __restrict__ C, bf16* __restrict__ Chi, bf16* __restrict__ Clo,
                  long ldC, long bsC, const float* __restrict__ bias, float scale, int K,
                  int ksplit, long spStrideC,
                  bf16* __restrict__ VTh, bf16* __restrict__ VTl)
{
    extern __shared__ char smem[];
    const uint32_t sbase = smem_u32(smem);
    const int tid  = threadIdx.x;
    const int bz   = blockIdx.z;
    const int sp   = bz % ksplit;
    const int bt   = bz / ksplit;
    const long koff = (long)sp * K;
    const int row0 = blockIdx.y * BT_M;
    const int col0 = blockIdx.x * BT_N;

    const bf16* Ah = Ahi + (long)bt * bsA + koff;
    const bf16* Al = Alo + (long)bt * bsA + koff;
    const bf16* Bh = Bhi + (long)bt * bsB + koff;
    const bf16* Bl = Blo + (long)bt * bsB + koff;

    const int NC = K / BK;

    // stage loader: A 256 rows x 8 granules (4 hi + 4 lo), B 128 rows x 8
    auto load_stage = [&](int buf, int k0) {
        const uint32_t sb = sbase + (uint32_t)buf * BSTAGE;
        #pragma unroll
        for (int i = 0; i < 4; i++) {             // A: 2048 granules
            const int g = tid + 512 * i;
            const int r = g >> 3, c = g & 7;
            const uint32_t off = SWZ128((uint32_t)(r * 128 + c * 16));
            const long ka = k0 + (c & 3) * 8;
            const bf16* Asrc = (c < 4) ? (Ah + (long)(row0 + r) * ldA + ka)
                                       : (Al + (long)(row0 + r) * ldA + ka);
            cp16(sb + off, Asrc);
        }
        #pragma unroll
        for (int i = 0; i < 2; i++) {             // B: 1024 granules
            const int g = tid + 512 * i;
            const int r = g >> 3, c = g & 7;
            const uint32_t off = SWZ128((uint32_t)(r * 128 + c * 16));
            const long ka = k0 + (c & 3) * 8;
            const bf16* Bsrc = (c < 4) ? (Bh + (long)(col0 + r) * ldB + ka)
                                       : (Bl + (long)(col0 + r) * ldB + ka);
            cp16(sb + 32768 + off, Bsrc);
        }
    };

    load_stage(0, 0);      CP_COMMIT();
    load_stage(1, BK);     CP_COMMIT();
    load_stage(2, 2 * BK); CP_COMMIT();

    const int w    = tid >> 5;
    const int lane = tid & 31;
    const int wm   = w & 3;            // rows wm*64
    const int wn   = w >> 2;           // cols wn*32
    const int q    = lane >> 3;
    const int r8   = lane & 7;

    float acc[4][4][4];
    #pragma unroll
    for (int i = 0; i < 4; i++)
        #pragma unroll
        for (int j = 0; j < 4; j++)
            #pragma unroll
            for (int v = 0; v < 4; v++) acc[i][j][v] = 0.0f;

    for (int c = 0; c < NC; c++) {
        if (c + 3 <= NC)      asm volatile("cp.async.wait_group 2;" ::: "memory");
        else if (c + 2 == NC) asm volatile("cp.async.wait_group 1;" ::: "memory");
        else                  asm volatile("cp.async.wait_group 0;" ::: "memory");
        __syncthreads();                          // single barrier per chunk
        if (c + 3 < NC) {
            load_stage((c + 3) & 3, (c + 3) * BK);   // target freed by chunk c-1
            CP_COMMIT();
        }

        const uint32_t sb = sbase + (uint32_t)(c & 3) * BSTAGE;
        #pragma unroll
        for (int ks = 0; ks < 2; ks++) {
            uint32_t bhf[2][4], blf[2][4];
            #pragma unroll
            for (int p = 0; p < 2; p++) {
                const int nn = wn * 32 + p * 16 + (q >> 1) * 8 + r8;
                const int cc = 2 * ks + (q & 1);
                ldm_x4(bhf[p], sb + 32768 + SWZ128((uint32_t)(nn * 128 + cc * 16)));
                ldm_x4(blf[p], sb + 32768 + SWZ128((uint32_t)(nn * 128 + 64 + cc * 16)));
            }
            #pragma unroll
            for (int am = 0; am < 4; am++) {
                uint32_t ah[4], al[4];
                const int rr = wm * 64 + am * 16 + (q & 1) * 8 + r8;
                const int cc = 2 * ks + (q >> 1);
                ldm_x4(ah, sb + SWZ128((uint32_t)(rr * 128 + cc * 16)));
                ldm_x4(al, sb + SWZ128((uint32_t)(rr * 128 + 64 + cc * 16)));
                #pragma unroll
                for (int bn = 0; bn < 4; bn++) {
                    const int p = bn >> 1, hf = (bn & 1) * 2;
                    mma16816(acc[am][bn], ah, bhf[p][hf], bhf[p][hf + 1]);
                    mma16816(acc[am][bn], al, bhf[p][hf], bhf[p][hf + 1]);
                    mma16816(acc[am][bn], ah, blf[p][hf], blf[p][hf + 1]);
                }
            }
        }
    }

    // -------- epilogue --------
    const int gg = lane >> 2, t = lane & 3;
    float* Cp = (EPI == 0 || EPI == 2) ? C + (long)bt * bsC + (long)sp * spStrideC : nullptr;
    bf16* Hp  = (EPI == 1 || EPI == 3) ? Chi + (long)bt * bsC : nullptr;
    bf16* Lp  = (EPI == 1 || EPI == 3) ? Clo + (long)bt * bsC : nullptr;
    const bool vout = VOUT && (col0 >= 2 * EMBED);

    #pragma unroll
    for (int am = 0; am < 4; am++) {
        const long r0 = row0 + wm * 64 + am * 16 + gg;
        const long r1 = r0 + 8;
        #pragma unroll
        for (int bn = 0; bn < 4; bn++) {
            const int col = col0 + wn * 32 + bn * 8 + 2 * t;
            float v[4];
            #pragma unroll
            for (int i = 0; i < 4; i++) v[i] = acc[am][bn][i];
            if (EPI == 2) {
                #pragma unroll
                for (int i = 0; i < 4; i++) v[i] *= scale;
            } else {
                const float b0 = __ldg(&bias[col]);
                const float b1 = __ldg(&bias[col + 1]);
                v[0] += b0; v[1] += b1; v[2] += b0; v[3] += b1;
                if (EPI == 3) {
                    #pragma unroll
                    for (int i = 0; i < 4; i++) v[i] = gelu_exact(v[i]);
                }
            }
            if (EPI == 0 || EPI == 2) {
                *(float2*)(Cp + r0 * ldC + col) = make_float2(v[0], v[1]);
                *(float2*)(Cp + r1 * ldC + col) = make_float2(v[2], v[3]);
            } else if (vout) {
                // transposed V output: VT[b][e][s], b=token>>10, s=token&1023
                const int e = col - 2 * EMBED;
                const long b0i = (r0 >> 10) * (long)EMBED * SEQ;
                const long s0 = r0 & 1023;
                const long b1i = (r1 >> 10) * (long)EMBED * SEQ;
                const long s1 = r1 & 1023;
                #pragma unroll
                for (int i = 0; i < 4; i++) {
                    const long o = ((i < 2) ? (b0i + s0) : (b1i + s1)) + (long)(e + (i & 1)) * SEQ;
                    bf16 h = __float2bfloat16(v[i]);
                    VTh[o] = h;
                    VTl[o] = __float2bfloat16(v[i] - __bfloat162float(h));
                }
            } else {
                bf16 a0 = __float2bfloat16(v[0]), a1 = __float2bfloat16(v[1]);
                bf16 a2 = __float2bfloat16(v[2]), a3 = __float2bfloat16(v[3]);
                *(ushort2*)(Hp + r0 * ldC + col) =
                    make_ushort2(__bfloat16_as_ushort(a0), __bfloat16_as_ushort(a1));
                *(ushort2*)(Hp + r1 * ldC + col) =
                    make_ushort2(__bfloat16_as_ushort(a2), __bfloat16_as_ushort(a3));
                *(ushort2*)(Lp + r0 * ldC + col) = make_ushort2(
                    __bfloat16_as_ushort(__float2bfloat16(v[0] - __bfloat162float(a0))),
                    __bfloat16_as_ushort(__float2bfloat16(v[1] - __bfloat162float(a1))));
                *(ushort2*)(Lp + r1 * ldC + col) = make_ushort2(
                    __bfloat16_as_ushort(__float2bfloat16(v[2] - __bfloat162float(a2))),
                    __bfloat16_as_ushort(__float2bfloat16(v[3] - __bfloat162float(a3))));
            }
        }
    }
}

// ============================ glue kernels ===================================
__global__ __launch_bounds__(256)
void split_kernel(const float* __restrict__ in, bf16* __restrict__ hi, bf16* __restrict__ lo, long n4)
{
    long i = (long)blockIdx.x * blockDim.x + threadIdx.x;
    if (i >= n4) return;
    float4 v = ((const float4*)in)[i];
    unsigned short h[4], l[4];
    float vv[4] = {v.x, v.y, v.z, v.w};
    #pragma unroll
    for (int j = 0; j < 4; j++) {
        bf16 hb = __float2bfloat16(vv[j]);
        h[j] = __bfloat16_as_ushort(hb);
        l[j] = __bfloat16_as_ushort(__float2bfloat16(vv[j] - __bfloat162float(hb)));
    }
    ((uint2*)hi)[i] = *(uint2*)h;
    ((uint2*)lo)[i] = *(uint2*)l;
}

// One launch: transpose+split all 5 weights [R,C]->[C,R] hi/lo, plus bias concat.
__global__ __launch_bounds__(256)
void mega_wsplit(const float* __restrict__ Wq, const float* __restrict__ Wk,
                 const float* __restrict__ Wv, const float* __restrict__ W1,
                 const float* __restrict__ W2,
                 const float* __restrict__ bq, const float* __restrict__ bk,
                 const float* __restrict__ bv,
                 bf16* __restrict__ W1h, bf16* __restrict__ W1l,
                 bf16* __restrict__ W2h, bf16* __restrict__ W2l,
                 float* __restrict__ bqkv)
{
    const int tflat = threadIdx.y * 32 + threadIdx.x;
    const int blk = blockIdx.x;
    if (blk == 6336) {
        for (int i = tflat; i < NQKV; i += 256)
            bqkv[i] = (i < EMBED) ? bq[i] : (i < 2 * EMBED) ? bk[i - EMBED] : bv[i - 2 * EMBED];
        return;
    }
    const float* in; bf16 *hi, *lo;
    int R, C, bx, by;
    if (blk < 1728) {
        const int ww = blk / 576, loc = blk % 576;
        in = (ww == 0) ? Wq : (ww == 1) ? Wk : Wv;
        hi = g_Wqkvh + (long)ww * EMBED * EMBED;
        lo = g_Wqkvl + (long)ww * EMBED * EMBED;
        R = EMBED; C = EMBED; bx = loc % 24; by = loc / 24;
    } else if (blk < 4032) {
        const int loc = blk - 1728;
        in = W1; hi = W1h; lo = W1l;
        R = EMBED; C = FF; bx = loc % 96; by = loc / 96;
    } else {
        const int loc = blk - 4032;
        in = W2; hi = W2h; lo = W2l;
        R = FF; C = EMBED; bx = loc % 24; by = loc / 24;
    }
    __shared__ float tshr[32][33];
    const int tx = threadIdx.x, ty = threadIdx.y;
    const int c = bx * 32 + tx;
    const int r0 = by * 32;
    #pragma unroll
    for (int i = 0; i < 4; i++)
        tshr[ty + i * 8][tx] = in[(long)(r0 + ty + i * 8) * C + c];
    __syncthreads();
    const int co0 = bx * 32;
    #pragma unroll
    for (int i = 0; i < 4; i++) {
        float v = tshr[tx][ty + i * 8];
        bf16 h = __float2bfloat16(v);
        long o = (long)(co0 + ty + i * 8) * R + r0 + tx;
        hi[o] = h;
        lo[o] = __float2bfloat16(v - __bfloat162float(h));
    }
}

__global__ __launch_bounds__(256)
void softmax_kernel(float* __restrict__ S, bf16* __restrict__ Phi, bf16* __restrict__ Plo)
{
    float* row = S + (long)blockIdx.x * SEQ;
    const int tid = threadIdx.x;
    float v[4];
    float m = -1e30f;
    #pragma unroll
    for (int j = 0; j < 4; j++) { v[j] = row[tid + 256 * j]; m = fmaxf(m, v[j]); }
    __shared__ float red[8];
    #pragma unroll
    for (int o = 16; o > 0; o >>= 1) m = fmaxf(m, __shfl_xor_sync(0xffffffffu, m, o));
    if ((tid & 31) == 0) red[tid >> 5] = m;
    __syncthreads();
    m = red[0];
    #pragma unroll
    for (int i = 1; i < 8; i++) m = fmaxf(m, red[i]);
    float s = 0.0f;
    #pragma unroll
    for (int j = 0; j < 4; j++) { v[j] = __expf(v[j] - m); s += v[j]; }
    __syncthreads();
    #pragma unroll
    for (int o = 16; o > 0; o >>= 1) s += __shfl_xor_sync(0xffffffffu, s, o);
    if ((tid & 31) == 0) red[tid >> 5] = s;
    __syncthreads();
    s = 0.0f;
    #pragma unroll
    for (int i = 0; i < 8; i++) s += red[i];
    const float inv = 1.0f / s;
    bf16* ph = Phi + (long)blockIdx.x * SEQ;
    bf16* pl = Plo + (long)blockIdx.x * SEQ;
    #pragma unroll
    for (int j = 0; j < 4; j++) {
        float p = v[j] * inv;
        bf16 h = __float2bfloat16(p);
        ph[tid + 256 * j] = h;
        pl[tid + 256 * j] = __float2bfloat16(p - __bfloat162float(h));
    }
}

// out = xin + LN(t0 (+t1) (+t2) (+bias)) * g + beta;  optional hi/lo split out.
template <int NT, bool HASB, bool SPLIT>
__global__ __launch_bounds__(256)
void ln_residual_kernel(const float* __restrict__ xin,
                        const float* __restrict__ t0, const float* __restrict__ t1,
                        const float* __restrict__ t2, const float* __restrict__ bvec,
                        const float* __restrict__ g, const float* __restrict__ beta,
                        float* __restrict__ out, bf16* __restrict__ ohi, bf16* __restrict__ olo)
{
    const long base = (long)blockIdx.x * EMBED;
    const int tid = threadIdx.x;
    float vv[3];
    #pragma unroll
    for (int j = 0; j < 3; j++) {
        const int o = tid + j * 256;
        float v = t0[base + o];
        if (NT >= 2) v += t1[base + o];
        if (NT >= 3) v += t2[base + o];
        if (HASB)    v += bvec[o];
        vv[j] = v;
    }
    float s = vv[0] + vv[1] + vv[2];
    float q = vv[0] * vv[0] + vv[1] * vv[1] + vv[2] * vv[2];
    __shared__ float rs[8], rq[8];
    #pragma unroll
    for (int o = 16; o > 0; o >>= 1) {
        s += __shfl_xor_sync(0xffffffffu, s, o);
        q += __shfl_xor_sync(0xffffffffu, q, o);
    }
    if ((tid & 31) == 0) { rs[tid >> 5] = s; rq[tid >> 5] = q; }
    __syncthreads();
    s = 0.0f; q = 0.0f;
    #pragma unroll
    for (int i = 0; i < 8; i++) { s += rs[i]; q += rq[i]; }
    const float mu  = s * (1.0f / EMBED);
    const float var = q * (1.0f / EMBED) - mu * mu;
    const float inv = rsqrtf(var + 1e-5f);
    #pragma unroll
    for (int j = 0; j < 3; j++) {
        const int o = tid + j * 256;
        float r = xin[base + o] + (vv[j] - mu) * inv * g[o] + beta[o];
        out[base + o] = r;
        if (SPLIT) {
            bf16 h = __float2bfloat16(r);
            ohi[base + o] = h;
            olo[base + o] = __float2bfloat16(r - __bfloat162float(h));
        }
    }
}

// ============================ launcher =======================================
extern "C" void kernel_launch(void* const* d_in, const int* in_sizes, int n_in,
                              void* d_out, int out_size)
{
    const float* x     = (const float*)d_in[0];
    const float* Wq    = (const float*)d_in[1];
    const float* bq    = (const float*)d_in[2];
    const float* Wk    = (const float*)d_in[3];
    const float* bk    = (const float*)d_in[4];
    const float* Wv    = (const float*)d_in[5];
    const float* bv    = (const float*)d_in[6];
    const float* W1    = (const float*)d_in[7];
    const float* b1    = (const float*)d_in[8];
    const float* W2    = (const float*)d_in[9];
    const float* b2    = (const float*)d_in[10];
    const float* g1    = (const float*)d_in[11];
    const float* beta1 = (const float*)d_in[12];
    const float* g2    = (const float*)d_in[13];
    const float* beta2 = (const float*)d_in[14];
    float* out = (float*)d_out;

    bf16 *xhi, *xlo, *Wqkvh, *Wqkvl, *W1Th, *W1Tl, *W2Th, *W2Tl;
    bf16 *QKVh, *QKVl, *VTh, *VTl, *Phi, *Plo, *x1hi, *x1lo, *hhi, *hlo;
    float *bqkv, *S, *attnP, *x1, *fP;
    cudaGetSymbolAddress((void**)&xhi, g_xhi);     cudaGetSymbolAddress((void**)&xlo, g_xlo);
    cudaGetSymbolAddress((void**)&Wqkvh, g_Wqkvh); cudaGetSymbolAddress((void**)&Wqkvl, g_Wqkvl);
    cudaGetSymbolAddress((void**)&bqkv, g_bqkv);
    cudaGetSymbolAddress((void**)&W1Th, g_W1Th);   cudaGetSymbolAddress((void**)&W1Tl, g_W1Tl);
    cudaGetSymbolAddress((void**)&W2Th, g_W2Th);   cudaGetSymbolAddress((void**)&W2Tl, g_W2Tl);
    cudaGetSymbolAddress((void**)&QKVh, g_QKVh);   cudaGetSymbolAddress((void**)&QKVl, g_QKVl);
    cudaGetSymbolAddress((void**)&VTh, g_VTh);     cudaGetSymbolAddress((void**)&VTl, g_VTl);
    cudaGetSymbolAddress((void**)&S, g_S);
    cudaGetSymbolAddress((void**)&Phi, g_Phi);     cudaGetSymbolAddress((void**)&Plo, g_Plo);
    cudaGetSymbolAddress((void**)&attnP, g_attnP);
    cudaGetSymbolAddress((void**)&x1, g_x1);
    cudaGetSymbolAddress((void**)&x1hi, g_x1hi);   cudaGetSymbolAddress((void**)&x1lo, g_x1lo);
    cudaGetSymbolAddress((void**)&hhi, g_hhi);     cudaGetSymbolAddress((void**)&hlo, g_hlo);
    cudaGetSymbolAddress((void**)&fP, g_fP);

    cudaFuncSetAttribute((const void*)mma_gemm_big<0, false>, cudaFuncAttributeMaxDynamicSharedMemorySize, BSMEM_TOTAL);
    cudaFuncSetAttribute((const void*)mma_gemm_big<1, true>,  cudaFuncAttributeMaxDynamicSharedMemorySize, BSMEM_TOTAL);
    cudaFuncSetAttribute((const void*)mma_gemm_big<2, false>, cudaFuncAttributeMaxDynamicSharedMemorySize, BSMEM_TOTAL);
    cudaFuncSetAttribute((const void*)mma_gemm_big<3, false>, cudaFuncAttributeMaxDynamicSharedMemorySize, BSMEM_TOTAL);

    const dim3 blk(256);
    const dim3 gblk(512);
    const dim3 tblk(32, 8);
    const float att_scale = 1.0f / sqrtf((float)EMBED);

    // 0: split x -> hi/lo
    split_kernel<<<(TOK * EMBED / 4 + 255) / 256, blk>>>(x, xhi, xlo, TOK * EMBED / 4);
    // 1: all weight splits + bias concat
    mega_wsplit<<<6337, tblk>>>(Wq, Wk, Wv, W1, W2, bq, bk, bv,
                                W1Th, W1Tl, W2Th, W2Tl, bqkv);
    // 2: fused QKV = x @ [Wq|Wk|Wv] + bias; Q,K -> hi/lo, V -> VT hi/lo (fused transpose)
    mma_gemm_big<1, true><<<dim3(NQKV / BT_N, TOK / BT_M, 1), gblk, BSMEM_TOTAL>>>(
        xhi, xlo, EMBED, 0, Wqkvh, Wqkvl, EMBED, 0,
        nullptr, QKVh, QKVl, NQKV, 0, bqkv, 0.f, EMBED, 1, 0, VTh, VTl);
    // 3: scores = Q @ K^T * scale
    mma_gemm_big<2, false><<<dim3(SEQ / BT_N, SEQ / BT_M, BATCH), gblk, BSMEM_TOTAL>>>(
        QKVh, QKVl, NQKV, (long)SEQ * NQKV,
        QKVh + EMBED, QKVl + EMBED, NQKV, (long)SEQ * NQKV,
        S, nullptr, nullptr, SEQ, (long)SEQ * SEQ, nullptr, att_scale, EMBED, 1, 0,
        nullptr, nullptr);
    // 4: softmax -> P hi/lo
    softmax_kernel<<<TOK, blk>>>(S, Phi, Plo);
    // 5: attn partials = P @ V, split-K=2
    mma_gemm_big<2, false><<<dim3(EMBED / BT_N, SEQ / BT_M, BATCH * 2), gblk, BSMEM_TOTAL>>>(
        Phi, Plo, SEQ, (long)SEQ * SEQ, VTh, VTl, SEQ, (long)EMBED * SEQ,
        attnP, nullptr, nullptr, EMBED, (long)SEQ * EMBED, nullptr, 1.0f, SEQ / 2,
        2, (long)TOK * EMBED, nullptr, nullptr);
    // 6: x1 = x + LN(attn0 + attn1)  (+ split)
    ln_residual_kernel<2, false, true><<<TOK, blk>>>(
        x, attnP, attnP + (long)TOK * EMBED, nullptr, nullptr, g1, beta1, x1, x1hi, x1lo);
    // 7: h = gelu(x1 @ W1 + b1) -> hi/lo
    mma_gemm_big<3, false><<<dim3(FF / BT_N, TOK / BT_M, 1), gblk, BSMEM_TOTAL>>>(
        x1hi, x1lo, EMBED, 0, W1Th, W1Tl, EMBED, 0,
        nullptr, hhi, hlo, FF, 0, b1, 0.f, EMBED, 1, 0, nullptr, nullptr);
    // 8: f partials = h @ W2, split-K=3
    mma_gemm_big<2, false><<<dim3(EMBED / BT_N, TOK / BT_M, 3), gblk, BSMEM_TOTAL>>>(
        hhi, hlo, FF, 0, W2Th, W2Tl, FF, 0,
        fP, nullptr, nullptr, EMBED, 0, nullptr, 1.0f, FF / 3, 3, (long)TOK * EMBED,
        nullptr, nullptr);
    // 9: out = x1 + LN(f0+f1+f2 + b2)
    ln_residual_kernel<3, true, false><<<TOK, blk>>>(
        x1, fP, fP + (long)TOK * EMBED, fP + 2L * TOK * EMBED, b2, g2, beta2,
        out, nullptr, nullptr);
}

// round 9
// speedup vs baseline: 1.5464x; 1.5464x over previous
#include <cuda_runtime.h>
#include <cuda_fp16.h>
#include <math.h>
#include <stdint.h>

#define EMBED 768
#define FF    3072
#define BATCH 8
#define SEQ   1024
#define TOK   (BATCH * SEQ)   // 8192
#define NQKV  (3 * EMBED)     // 2304

typedef __half fp16;

// ============================ scratch buffers ================================
__device__ __align__(16) fp16  g_xhi[TOK * EMBED],  g_xlo[TOK * EMBED];
__device__ __align__(16) fp16  g_Wqkvh[(long)NQKV * EMBED];
__device__ __align__(16) float g_bqkv[NQKV];
__device__ __align__(16) fp16  g_W1Th[(long)FF * EMBED];
__device__ __align__(16) fp16  g_W2Th[(long)EMBED * FF];
__device__ __align__(16) fp16  g_QKVh[(long)TOK * NQKV], g_QKVl[(long)TOK * NQKV];
__device__ __align__(16) fp16  g_VTh[(long)BATCH * EMBED * SEQ];
__device__ __align__(16) float g_S[(long)BATCH * SEQ * SEQ];
__device__ __align__(16) fp16  g_Phi[(long)BATCH * SEQ * SEQ], g_Plo[(long)BATCH * SEQ * SEQ];
__device__ __align__(16) float g_attnP[2L * TOK * EMBED];
__device__ __align__(16) float g_x1[TOK * EMBED];
__device__ __align__(16) fp16  g_x1hi[TOK * EMBED], g_x1lo[TOK * EMBED];
__device__ __align__(16) fp16  g_hhi[(long)TOK * FF], g_hlo[(long)TOK * FF];
__device__ __align__(16) float g_fP[3L * TOK * EMBED];

// ============================ PTX helpers ====================================
__device__ __forceinline__ uint32_t smem_u32(const void* p) {
    uint32_t a;
    asm("{ .reg .u64 t; cvta.to.shared.u64 t, %1; cvt.u32.u64 %0, t; }" : "=r"(a) : "l"(p));
    return a;
}
__device__ __forceinline__ void cp16(uint32_t dst, const void* src) {
    asm volatile("cp.async.cg.shared.global [%0], [%1], 16;" :: "r"(dst), "l"(src));
}
#define CP_COMMIT() asm volatile("cp.async.commit_group;" ::: "memory")

__device__ __forceinline__ void ldm_x4(uint32_t* r, uint32_t addr) {
    asm volatile("ldmatrix.sync.aligned.m8n8.x4.shared.b16 {%0,%1,%2,%3}, [%4];"
                 : "=r"(r[0]), "=r"(r[1]), "=r"(r[2]), "=r"(r[3]) : "r"(addr));
}
__device__ __forceinline__ void mma16816(float* d, const uint32_t* a, uint32_t b0, uint32_t b1) {
    asm volatile(
        "mma.sync.aligned.m16n8k16.row.col.f32.f16.f16.f32 "
        "{%0,%1,%2,%3}, {%4,%5,%6,%7}, {%8,%9}, {%0,%1,%2,%3};"
        : "+f"(d[0]), "+f"(d[1]), "+f"(d[2]), "+f"(d[3])
        : "r"(a[0]), "r"(a[1]), "r"(a[2]), "r"(a[3]), "r"(b0), "r"(b1));
}
#define SWZ128(o) ((o) ^ (((o) >> 3) & 0x70))

__device__ __forceinline__ float gelu_exact(float v) {
    return 0.5f * v * (1.0f + erff(v * 0.7071067811865475f));
}
__device__ __forceinline__ ushort h2u(fp16 h) { return __half_as_ushort(h); }

// ============================ mma GEMM =======================================
// C[M,N] = (Ahi+Alo)[M,K] @ fp16(B)[N,K]^T   (both K-major row-major)
// 2-pass fp16 split: full-precision A x fp16-rounded B.
// CTA 256x128, 256 threads (8 warps, warp tile 64x64), BK=64, 2 stages.
// Stage: Ahi 32K | Alo 32K | Bhi 16K = 80K; 2 stages = 160K.
// blockIdx.z = batch*ksplit + split;  K = per-split K length.
// EPI: 1 bias->(hi,lo) | 2 scale->fp32 | 3 bias+gelu->(hi,lo)
// VOUT (with EPI=1): CTAs with col0>=1536 write transposed VT (hi only).
#define BT_M 256
#define BT_N 128
#define BK   64
#define BSTAGE 81920
#define BSMEM_TOTAL (2 * BSTAGE)

template <int EPI, bool VOUT>
__global__ __launch_bounds__(256, 1)
void mma_gemm_big(const fp16* __restrict__ Ahi, const fp16* __restrict__ Alo, long ldA, long bsA,
                  const fp16* __restrict__ Bhi, long ldB, long bsB,
                  float* __restrict__ C, fp16* __restrict__ Chi, fp16* __restrict__ Clo,
                  long ldC, long bsC, const float* __restrict__ bias, float scale, int K,
                  int ksplit, long spStrideC, fp16* __restrict__ VTh)
{
    extern __shared__ char smem[];
    const uint32_t sbase = smem_u32(smem);
    const int tid  = threadIdx.x;
    const int bz   = blockIdx.z;
    const int sp   = bz % ksplit;
    const int bt   = bz / ksplit;
    const long koff = (long)sp * K;
    const int row0 = blockIdx.y * BT_M;
    const int col0 = blockIdx.x * BT_N;

    const fp16* Ah = Ahi + (long)bt * bsA + koff;
    const fp16* Al = Alo + (long)bt * bsA + koff;
    const fp16* Bh = Bhi + (long)bt * bsB + koff;

    const int NC = K / BK;

    auto load_stage = [&](int buf, int k0) {
        const uint32_t sb = sbase + (uint32_t)buf * BSTAGE;
        #pragma unroll
        for (int i = 0; i < 8; i++) {            // A: 2048 granules per half
            const int g = tid + 256 * i;
            const int r = g >> 3, c = g & 7;
            const uint32_t off = SWZ128((uint32_t)(r * 128 + c * 16));
            const long ai = (long)(row0 + r) * ldA + k0 + c * 8;
            cp16(sb + off,         Ah + ai);
            cp16(sb + 32768 + off, Al + ai);
        }
        #pragma unroll
        for (int i = 0; i < 4; i++) {            // B: 1024 granules (hi only)
            const int g = tid + 256 * i;
            const int r = g >> 3, c = g & 7;
            const uint32_t off = SWZ128((uint32_t)(r * 128 + c * 16));
            const long bi = (long)(col0 + r) * ldB + k0 + c * 8;
            cp16(sb + 65536 + off, Bh + bi);
        }
    };

    load_stage(0, 0);
    CP_COMMIT();
    if (NC > 1) { load_stage(1, BK); CP_COMMIT(); }

    const int w    = tid >> 5;
    const int lane = tid & 31;
    const int wm   = w & 3;            // rows wm*64
    const int wn   = w >> 2;           // cols wn*64
    const int q    = lane >> 3;
    const int r8   = lane & 7;

    float acc[4][8][4];
    #pragma unroll
    for (int i = 0; i < 4; i++)
        #pragma unroll
        for (int j = 0; j < 8; j++)
            #pragma unroll
            for (int v = 0; v < 4; v++) acc[i][j][v] = 0.0f;

    for (int c = 0; c < NC; c++) {
        if (c + 1 < NC) asm volatile("cp.async.wait_group 1;" ::: "memory");
        else            asm volatile("cp.async.wait_group 0;" ::: "memory");
        __syncthreads();

        const uint32_t sb = sbase + (uint32_t)(c & 1) * BSTAGE;
        #pragma unroll
        for (int ks = 0; ks < 4; ks++) {
            uint32_t bhf[4][4];
            #pragma unroll
            for (int p = 0; p < 4; p++) {
                const int nn = wn * 64 + p * 16 + (q >> 1) * 8 + r8;
                const int cc = 2 * ks + (q & 1);
                ldm_x4(bhf[p], sb + 65536 + SWZ128((uint32_t)(nn * 128 + cc * 16)));
            }
            #pragma unroll
            for (int am = 0; am < 4; am++) {
                uint32_t ah[4], al[4];
                const int rr = wm * 64 + am * 16 + (q & 1) * 8 + r8;
                const int cc = 2 * ks + (q >> 1);
                const uint32_t off = SWZ128((uint32_t)(rr * 128 + cc * 16));
                ldm_x4(ah, sb + off);
                ldm_x4(al, sb + 32768 + off);
                #pragma unroll
                for (int bn = 0; bn < 8; bn++) {
                    const int p = bn >> 1, hf = (bn & 1) * 2;
                    mma16816(acc[am][bn], ah, bhf[p][hf], bhf[p][hf + 1]);
                    mma16816(acc[am][bn], al, bhf[p][hf], bhf[p][hf + 1]);
                }
            }
        }
        __syncthreads();
        if (c + 2 < NC) {
            load_stage(c & 1, (c + 2) * BK);
            CP_COMMIT();
        }
    }

    // -------- epilogue --------
    const int gg = lane >> 2, t = lane & 3;
    float* Cp = (EPI == 2) ? C + (long)bt * bsC + (long)sp * spStrideC : nullptr;
    fp16* Hp  = (EPI == 1 || EPI == 3) ? Chi + (long)bt * bsC : nullptr;
    fp16* Lp  = (EPI == 1 || EPI == 3) ? Clo + (long)bt * bsC : nullptr;
    const bool vout = VOUT && (col0 >= 2 * EMBED);

    #pragma unroll
    for (int am = 0; am < 4; am++) {
        const long r0 = row0 + wm * 64 + am * 16 + gg;
        const long r1 = r0 + 8;
        #pragma unroll
        for (int bn = 0; bn < 8; bn++) {
            const int col = col0 + wn * 64 + bn * 8 + 2 * t;
            float v[4];
            #pragma unroll
            for (int i = 0; i < 4; i++) v[i] = acc[am][bn][i];
            if (EPI == 2) {
                #pragma unroll
                for (int i = 0; i < 4; i++) v[i] *= scale;
            } else {
                const float b0 = __ldg(&bias[col]);
                const float b1 = __ldg(&bias[col + 1]);
                v[0] += b0; v[1] += b1; v[2] += b0; v[3] += b1;
                if (EPI == 3) {
                    #pragma unroll
                    for (int i = 0; i < 4; i++) v[i] = gelu_exact(v[i]);
                }
            }
            if (EPI == 2) {
                *(float2*)(Cp + r0 * ldC + col) = make_float2(v[0], v[1]);
                *(float2*)(Cp + r1 * ldC + col) = make_float2(v[2], v[3]);
            } else if (vout) {
                // transposed V output (hi only): VT[b][e][s]
                const int e = col - 2 * EMBED;
                const long b0i = (r0 >> 10) * (long)EMBED * SEQ;
                const long s0 = r0 & 1023;
                const long b1i = (r1 >> 10) * (long)EMBED * SEQ;
                const long s1 = r1 & 1023;
                #pragma unroll
                for (int i = 0; i < 4; i++) {
                    const long o = ((i < 2) ? (b0i + s0) : (b1i + s1)) + (long)(e + (i & 1)) * SEQ;
                    VTh[o] = __float2half_rn(v[i]);
                }
            } else {
                fp16 a0 = __float2half_rn(v[0]), a1 = __float2half_rn(v[1]);
                fp16 a2 = __float2half_rn(v[2]), a3 = __float2half_rn(v[3]);
                *(ushort2*)(Hp + r0 * ldC + col) = make_ushort2(h2u(a0), h2u(a1));
                *(ushort2*)(Hp + r1 * ldC + col) = make_ushort2(h2u(a2), h2u(a3));
                *(ushort2*)(Lp + r0 * ldC + col) = make_ushort2(
                    h2u(__float2half_rn(v[0] - __half2float(a0))),
                    h2u(__float2half_rn(v[1] - __half2float(a1))));
                *(ushort2*)(Lp + r1 * ldC + col) = make_ushort2(
                    h2u(__float2half_rn(v[2] - __half2float(a2))),
                    h2u(__float2half_rn(v[3] - __half2float(a3))));
            }
        }
    }
}

// ============================ glue kernels ===================================
__global__ __launch_bounds__(256)
void split_kernel(const float* __restrict__ in, fp16* __restrict__ hi, fp16* __restrict__ lo, long n4)
{
    long i = (long)blockIdx.x * blockDim.x + threadIdx.x;
    if (i >= n4) return;
    float4 v = ((const float4*)in)[i];
    unsigned short h[4], l[4];
    float vv[4] = {v.x, v.y, v.z, v.w};
    #pragma unroll
    for (int j = 0; j < 4; j++) {
        fp16 hb = __float2half_rn(vv[j]);
        h[j] = __half_as_ushort(hb);
        l[j] = __half_as_ushort(__float2half_rn(vv[j] - __half2float(hb)));
    }
    ((uint2*)hi)[i] = *(uint2*)h;
    ((uint2*)lo)[i] = *(uint2*)l;
}

// One launch: transpose all 5 weights [R,C]->[C,R] fp16 (hi only) + bias concat.
__global__ __launch_bounds__(256)
void mega_wsplit(const float* __restrict__ Wq, const float* __restrict__ Wk,
                 const float* __restrict__ Wv, const float* __restrict__ W1,
                 const float* __restrict__ W2,
                 const float* __restrict__ bq, const float* __restrict__ bk,
                 const float* __restrict__ bv,
                 fp16* __restrict__ W1h, fp16* __restrict__ W2h,
                 float* __restrict__ bqkv)
{
    const int tflat = threadIdx.y * 32 + threadIdx.x;
    const int blk = blockIdx.x;
    if (blk == 6336) {
        for (int i = tflat; i < NQKV; i += 256)
            bqkv[i] = (i < EMBED) ? bq[i] : (i < 2 * EMBED) ? bk[i - EMBED] : bv[i - 2 * EMBED];
        return;
    }
    const float* in; fp16* hi;
    int R, C, bx, by;
    if (blk < 1728) {
        const int ww = blk / 576, loc = blk % 576;
        in = (ww == 0) ? Wq : (ww == 1) ? Wk : Wv;
        hi = g_Wqkvh + (long)ww * EMBED * EMBED;
        R = EMBED; C = EMBED; bx = loc % 24; by = loc / 24;
    } else if (blk < 4032) {
        const int loc = blk - 1728;
        in = W1; hi = W1h;
        R = EMBED; C = FF; bx = loc % 96; by = loc / 96;
    } else {
        const int loc = blk - 4032;
        in = W2; hi = W2h;
        R = FF; C = EMBED; bx = loc % 24; by = loc / 24;
    }
    __shared__ float tshr[32][33];
    const int tx = threadIdx.x, ty = threadIdx.y;
    const int c = bx * 32 + tx;
    const int r0 = by * 32;
    #pragma unroll
    for (int i = 0; i < 4; i++)
        tshr[ty + i * 8][tx] = in[(long)(r0 + ty + i * 8) * C + c];
    __syncthreads();
    const int co0 = bx * 32;
    #pragma unroll
    for (int i = 0; i < 4; i++) {
        float v = tshr[tx][ty + i * 8];
        long o = (long)(co0 + ty + i * 8) * R + r0 + tx;
        hi[o] = __float2half_rn(v);
    }
}

__global__ __launch_bounds__(256)
void softmax_kernel(float* __restrict__ S, fp16* __restrict__ Phi, fp16* __restrict__ Plo)
{
    float* row = S + (long)blockIdx.x * SEQ;
    const int tid = threadIdx.x;
    float v[4];
    float m = -1e30f;
    #pragma unroll
    for (int j = 0; j < 4; j++) { v[j] = row[tid + 256 * j]; m = fmaxf(m, v[j]); }
    __shared__ float red[8];
    #pragma unroll
    for (int o = 16; o > 0; o >>= 1) m = fmaxf(m, __shfl_xor_sync(0xffffffffu, m, o));
    if ((tid & 31) == 0) red[tid >> 5] = m;
    __syncthreads();
    m = red[0];
    #pragma unroll
    for (int i = 1; i < 8; i++) m = fmaxf(m, red[i]);
    float s = 0.0f;
    #pragma unroll
    for (int j = 0; j < 4; j++) { v[j] = __expf(v[j] - m); s += v[j]; }
    __syncthreads();
    #pragma unroll
    for (int o = 16; o > 0; o >>= 1) s += __shfl_xor_sync(0xffffffffu, s, o);
    if ((tid & 31) == 0) red[tid >> 5] = s;
    __syncthreads();
    s = 0.0f;
    #pragma unroll
    for (int i = 0; i < 8; i++) s += red[i];
    const float inv = 1.0f / s;
    fp16* ph = Phi + (long)blockIdx.x * SEQ;
    fp16* pl = Plo + (long)blockIdx.x * SEQ;
    #pragma unroll
    for (int j = 0; j < 4; j++) {
        float p = v[j] * inv;
        fp16 h = __float2half_rn(p);
        ph[tid + 256 * j] = h;
        pl[tid + 256 * j] = __float2half_rn(p - __half2float(h));
    }
}

// out = xin + LN(t0 (+t1) (+t2) (+bias)) * g + beta;  optional hi/lo split out.
template <int NT, bool HASB, bool SPLIT>
__global__ __launch_bounds__(256)
void ln_residual_kernel(const float* __restrict__ xin,
                        const float* __restrict__ t0, const float* __restrict__ t1,
                        const float* __restrict__ t2, const float* __restrict__ bvec,
                        const float* __restrict__ g, const float* __restrict__ beta,
                        float* __restrict__ out, fp16* __restrict__ ohi, fp16* __restrict__ olo)
{
    const long base = (long)blockIdx.x * EMBED;
    const int tid = threadIdx.x;
    float vv[3];
    #pragma unroll
    for (int j = 0; j < 3; j++) {
        const int o = tid + j * 256;
        float v = t0[base + o];
        if (NT >= 2) v += t1[base + o];
        if (NT >= 3) v += t2[base + o];
        if (HASB)    v += bvec[o];
        vv[j] = v;
    }
    float s = vv[0] + vv[1] + vv[2];
    float q = vv[0] * vv[0] + vv[1] * vv[1] + vv[2] * vv[2];
    __shared__ float rs[8], rq[8];
    #pragma unroll
    for (int o = 16; o > 0; o >>= 1) {
        s += __shfl_xor_sync(0xffffffffu, s, o);
        q += __shfl_xor_sync(0xffffffffu, q, o);
    }
    if ((tid & 31) == 0) { rs[tid >> 5] = s; rq[tid >> 5] = q; }
    __syncthreads();
    s = 0.0f; q = 0.0f;
    #pragma unroll
    for (int i = 0; i < 8; i++) { s += rs[i]; q += rq[i]; }
    const float mu  = s * (1.0f / EMBED);
    const float var = q * (1.0f / EMBED) - mu * mu;
    const float inv = rsqrtf(var + 1e-5f);
    #pragma unroll
    for (int j = 0; j < 3; j++) {
        const int o = tid + j * 256;
        float r = xin[base + o] + (vv[j] - mu) * inv * g[o] + beta[o];
        out[base + o] = r;
        if (SPLIT) {
            fp16 h = __float2half_rn(r);
            ohi[base + o] = h;
            olo[base + o] = __float2half_rn(r - __half2float(h));
        }
    }
}

// ============================ launcher =======================================
extern "C" void kernel_launch(void* const* d_in, const int* in_sizes, int n_in,
                              void* d_out, int out_size)
{
    const float* x     = (const float*)d_in[0];
    const float* Wq    = (const float*)d_in[1];
    const float* bq    = (const float*)d_in[2];
    const float* Wk    = (const float*)d_in[3];
    const float* bk    = (const float*)d_in[4];
    const float* Wv    = (const float*)d_in[5];
    const float* bv    = (const float*)d_in[6];
    const float* W1    = (const float*)d_in[7];
    const float* b1    = (const float*)d_in[8];
    const float* W2    = (const float*)d_in[9];
    const float* b2    = (const float*)d_in[10];
    const float* g1    = (const float*)d_in[11];
    const float* beta1 = (const float*)d_in[12];
    const float* g2    = (const float*)d_in[13];
    const float* beta2 = (const float*)d_in[14];
    float* out = (float*)d_out;

    fp16 *xhi, *xlo, *Wqkvh, *W1Th, *W2Th;
    fp16 *QKVh, *QKVl, *VTh, *Phi, *Plo, *x1hi, *x1lo, *hhi, *hlo;
    float *bqkv, *S, *attnP, *x1, *fP;
    cudaGetSymbolAddress((void**)&xhi, g_xhi);     cudaGetSymbolAddress((void**)&xlo, g_xlo);
    cudaGetSymbolAddress((void**)&Wqkvh, g_Wqkvh);
    cudaGetSymbolAddress((void**)&bqkv, g_bqkv);
    cudaGetSymbolAddress((void**)&W1Th, g_W1Th);
    cudaGetSymbolAddress((void**)&W2Th, g_W2Th);
    cudaGetSymbolAddress((void**)&QKVh, g_QKVh);   cudaGetSymbolAddress((void**)&QKVl, g_QKVl);
    cudaGetSymbolAddress((void**)&VTh, g_VTh);
    cudaGetSymbolAddress((void**)&S, g_S);
    cudaGetSymbolAddress((void**)&Phi, g_Phi);     cudaGetSymbolAddress((void**)&Plo, g_Plo);
    cudaGetSymbolAddress((void**)&attnP, g_attnP);
    cudaGetSymbolAddress((void**)&x1, g_x1);
    cudaGetSymbolAddress((void**)&x1hi, g_x1hi);   cudaGetSymbolAddress((void**)&x1lo, g_x1lo);
    cudaGetSymbolAddress((void**)&hhi, g_hhi);     cudaGetSymbolAddress((void**)&hlo, g_hlo);
    cudaGetSymbolAddress((void**)&fP, g_fP);

    cudaFuncSetAttribute((const void*)mma_gemm_big<1, true>,  cudaFuncAttributeMaxDynamicSharedMemorySize, BSMEM_TOTAL);
    cudaFuncSetAttribute((const void*)mma_gemm_big<2, false>, cudaFuncAttributeMaxDynamicSharedMemorySize, BSMEM_TOTAL);
    cudaFuncSetAttribute((const void*)mma_gemm_big<3, false>, cudaFuncAttributeMaxDynamicSharedMemorySize, BSMEM_TOTAL);

    const dim3 blk(256);
    const dim3 tblk(32, 8);
    const float att_scale = 1.0f / sqrtf((float)EMBED);

    // 0: split x -> hi/lo
    split_kernel<<<(TOK * EMBED / 4 + 255) / 256, blk>>>(x, xhi, xlo, TOK * EMBED / 4);
    // 1: all weight transposes (hi only) + bias concat
    mega_wsplit<<<6337, tblk>>>(Wq, Wk, Wv, W1, W2, bq, bk, bv, W1Th, W2Th, bqkv);
    // 2: fused QKV = x @ [Wq|Wk|Wv] + bias; Q,K -> hi/lo, V -> VT hi (fused transpose)
    mma_gemm_big<1, true><<<dim3(NQKV / BT_N, TOK / BT_M, 1), blk, BSMEM_TOTAL>>>(
        xhi, xlo, EMBED, 0, Wqkvh, EMBED, 0,
        nullptr, QKVh, QKVl, NQKV, 0, bqkv, 0.f, EMBED, 1, 0, VTh);
    // 3: scores = Q @ K^T * scale
    mma_gemm_big<2, false><<<dim3(SEQ / BT_N, SEQ / BT_M, BATCH), blk, BSMEM_TOTAL>>>(
        QKVh, QKVl, NQKV, (long)SEQ * NQKV,
        QKVh + EMBED, NQKV, (long)SEQ * NQKV,
        S, nullptr, nullptr, SEQ, (long)SEQ * SEQ, nullptr, att_scale, EMBED, 1, 0, nullptr);
    // 4: softmax -> P hi/lo
    softmax_kernel<<<TOK, blk>>>(S, Phi, Plo);
    // 5: attn partials = P @ V, split-K=2
    mma_gemm_big<2, false><<<dim3(EMBED / BT_N, SEQ / BT_M, BATCH * 2), blk, BSMEM_TOTAL>>>(
        Phi, Plo, SEQ, (long)SEQ * SEQ, VTh, SEQ, (long)EMBED * SEQ,
        attnP, nullptr, nullptr, EMBED, (long)SEQ * EMBED, nullptr, 1.0f, SEQ / 2,
        2, (long)TOK * EMBED, nullptr);
    // 6: x1 = x + LN(attn0 + attn1)  (+ split)
    ln_residual_kernel<2, false, true><<<TOK, blk>>>(
        x, attnP, attnP + (long)TOK * EMBED, nullptr, nullptr, g1, beta1, x1, x1hi, x1lo);
    // 7: h = gelu(x1 @ W1 + b1) -> hi/lo
    mma_gemm_big<3, false><<<dim3(FF / BT_N, TOK / BT_M, 1), blk, BSMEM_TOTAL>>>(
        x1hi, x1lo, EMBED, 0, W1Th, EMBED, 0,
        nullptr, hhi, hlo, FF, 0, b1, 0.f, EMBED, 1, 0, nullptr);
    // 8: f partials = h @ W2, split-K=3
    mma_gemm_big<2, false><<<dim3(EMBED / BT_N, TOK / BT_M, 3), blk, BSMEM_TOTAL>>>(
        hhi, hlo, FF, 0, W2Th, FF, 0,
        fP, nullptr, nullptr, EMBED, 0, nullptr, 1.0f, FF / 3, 3, (long)TOK * EMBED, nullptr);
    // 9: out = x1 + LN(f0+f1+f2 + b2)
    ln_residual_kernel<3, true, false><<<TOK, blk>>>(
        x1, fP, fP + (long)TOK * EMBED, fP + 2L * TOK * EMBED, b2, g2, beta2,
        out, nullptr, nullptr);
}